// round 6
// baseline (speedup 1.0000x reference)
#include <cuda_runtime.h>
#include <cstdint>

#define N_NODES 100000
#define N_EDGES 3200000
#define IN_F    128
#define NB1     ((N_NODES + 255) / 256)   // 391 scan blocks

// ---------------- scratch (no allocations allowed) ----------------
__device__ float g_bufA[N_NODES * 32];   // node table A (y|r, later a|b)
__device__ float g_bufB[N_NODES * 32];   // node table B
__device__ int   g_deg[N_NODES];         // in-degree
__device__ int   g_start[N_NODES];       // CSR row start (exclusive prefix)
__device__ int   g_fill[N_NODES];        // fill cursor
__device__ int   g_csrc[N_EDGES];        // CSR: src ids grouped by dst
__device__ int   g_bsum[NB1];            // scan block sums
__device__ int   g_boff[NB1];            // scan block offsets

// ---------------- CSR build ----------------

__global__ void k_zero_deg() {
    int i = blockIdx.x * blockDim.x + threadIdx.x;
    if (i < N_NODES) g_deg[i] = 0;
}

__global__ void k_count(const int* __restrict__ ei) {
    int e = blockIdx.x * blockDim.x + threadIdx.x;
    if (e < N_EDGES) atomicAdd(&g_deg[__ldg(ei + N_EDGES + e)], 1);
}

// per-block inclusive scan of degrees -> intra-block exclusive into g_start, block sums
__global__ void k_scan1() {
    int b = blockIdx.x, t = threadIdx.x, i = b * 256 + t;
    int v = (i < N_NODES) ? g_deg[i] : 0;
    int lane = t & 31, w = t >> 5;
    int s = v;
#pragma unroll
    for (int o = 1; o < 32; o <<= 1) { int u = __shfl_up_sync(~0u, s, o); if (lane >= o) s += u; }
    __shared__ int ws[8], woff[8];
    if (lane == 31) ws[w] = s;
    __syncthreads();
    if (t == 0) { int run = 0; for (int k = 0; k < 8; k++) { woff[k] = run; run += ws[k]; } g_bsum[b] = run; }
    __syncthreads();
    if (i < N_NODES) g_start[i] = s - v + woff[w];
}

// scan the 391 block sums (single block, 512 threads)
__global__ void k_scan2() {
    int t = threadIdx.x;
    int v = (t < NB1) ? g_bsum[t] : 0;
    int lane = t & 31, w = t >> 5;
    int s = v;
#pragma unroll
    for (int o = 1; o < 32; o <<= 1) { int u = __shfl_up_sync(~0u, s, o); if (lane >= o) s += u; }
    __shared__ int ws[16], woff[16];
    if (lane == 31) ws[w] = s;
    __syncthreads();
    if (t == 0) { int run = 0; for (int k = 0; k < 16; k++) { woff[k] = run; run += ws[k]; } }
    __syncthreads();
    if (t < NB1) g_boff[t] = s - v + woff[w];
}

__global__ void k_scan3() {
    int i = blockIdx.x * blockDim.x + threadIdx.x;
    if (i < N_NODES) {
        int st = g_start[i] + g_boff[i >> 8];
        g_start[i] = st;
        g_fill[i]  = st;
    }
}

__global__ void k_fill(const int* __restrict__ ei) {
    int e = blockIdx.x * blockDim.x + threadIdx.x;
    if (e >= N_EDGES) return;
    int d = __ldg(ei + N_EDGES + e);
    int pos = atomicAdd(&g_fill[d], 1);
    g_csrc[pos] = __ldg(ei + e);
}

// ---------------- dense transforms ----------------

// y|r = x @ [w1_l | w1_r]   (128 -> 32), weights staged in shared -> g_bufA
__global__ void k_gemm_in(const float* __restrict__ x,
                          const float* __restrict__ wl,
                          const float* __restrict__ wr) {
    __shared__ float sw[IN_F * 32];
    for (int i = threadIdx.x; i < IN_F * 32; i += blockDim.x) {
        int k = i >> 5, c = i & 31;
        sw[i] = (c < 16) ? wl[k * 16 + c] : wr[k * 16 + (c - 16)];
    }
    __syncthreads();
    int n = blockIdx.x * blockDim.x + threadIdx.x;
    if (n >= N_NODES) return;

    float acc[32];
#pragma unroll
    for (int j = 0; j < 32; j++) acc[j] = 0.f;

    const float4* xr  = (const float4*)(x + (size_t)n * IN_F);
    const float4* sw4 = (const float4*)sw;

#pragma unroll 4
    for (int k4 = 0; k4 < IN_F / 4; k4++) {
        float4 xv = __ldg(xr + k4);
        float xs[4] = {xv.x, xv.y, xv.z, xv.w};
#pragma unroll
        for (int i = 0; i < 4; i++) {
            float xk = xs[i];
#pragma unroll
            for (int j = 0; j < 8; j++) {
                float4 w = sw4[(k4 * 4 + i) * 8 + j];   // uniform addr -> smem broadcast
                acc[4 * j + 0] = fmaf(xk, w.x, acc[4 * j + 0]);
                acc[4 * j + 1] = fmaf(xk, w.y, acc[4 * j + 1]);
                acc[4 * j + 2] = fmaf(xk, w.z, acc[4 * j + 2]);
                acc[4 * j + 3] = fmaf(xk, w.w, acc[4 * j + 3]);
            }
        }
    }
    float4* o = (float4*)(g_bufA + (size_t)n * 32);
#pragma unroll
    for (int j = 0; j < 8; j++)
        o[j] = make_float4(acc[4 * j], acc[4 * j + 1], acc[4 * j + 2], acc[4 * j + 3]);
}

// Fused: CSR gather-mean + combine(bias, residual, relu) + 16->32 GEMM.
// One warp per node. dir=0: in=A out=B ; dir=1: in=B out=A.
// sw[k][c] = (c<16) ? wa[k][c] : wb[k+offB][c-16]; bo (if non-null) added to cols 0..15 of output.
__global__ void k_agg(int dir,
                      const float* __restrict__ wa, const float* __restrict__ wb,
                      const float* __restrict__ bc, const float* __restrict__ bo,
                      int offB) {
    __shared__ float sw[16 * 32];
    __shared__ float sbc[16], sbo[16];
    const float* in  = dir ? g_bufB : g_bufA;
    float*       out = dir ? g_bufA : g_bufB;
    for (int i = threadIdx.x; i < 16 * 32; i += blockDim.x) {
        int k = i >> 5, c = i & 31;
        sw[i] = (c < 16) ? wa[k * 16 + c] : wb[(k + offB) * 16 + (c - 16)];
    }
    if (threadIdx.x < 16) {
        sbc[threadIdx.x] = bc[threadIdx.x];
        sbo[threadIdx.x] = bo ? bo[threadIdx.x] : 0.f;
    }
    __syncthreads();

    int w = (blockIdx.x * blockDim.x + threadIdx.x) >> 5;
    if (w >= N_NODES) return;
    int lane = threadIdx.x & 31;
    int c = lane & 3, gq = lane >> 2;           // chunk 0..3, group 0..7

    int deg = g_deg[w], start = g_start[w];
    float4 acc = make_float4(0.f, 0.f, 0.f, 0.f);
    for (int j = gq; j < deg; j += 8) {
        int s = __ldg(g_csrc + start + j);
        float4 v = *(const float4*)(in + (size_t)s * 32 + 4 * c);
        acc.x += v.x; acc.y += v.y; acc.z += v.z; acc.w += v.w;
    }
    // reduce the 8 groups (xor over lane bits 2..4)
#pragma unroll
    for (int m = 4; m <= 16; m <<= 1) {
        acc.x += __shfl_xor_sync(~0u, acc.x, m);
        acc.y += __shfl_xor_sync(~0u, acc.y, m);
        acc.z += __shfl_xor_sync(~0u, acc.z, m);
        acc.w += __shfl_xor_sync(~0u, acc.w, m);
    }
    // combine: mean + bias + residual, relu  (per-chunk, redundantly in 4 lanes)
    float inv = 1.f / fmaxf((float)deg, 1.f);
    float4 r = *(const float4*)(in + (size_t)w * 32 + 16 + 4 * c);
    float h0 = fmaxf(fmaf(acc.x, inv, sbc[4 * c + 0] + r.x), 0.f);
    float h1 = fmaxf(fmaf(acc.y, inv, sbc[4 * c + 1] + r.y), 0.f);
    float h2 = fmaxf(fmaf(acc.z, inv, sbc[4 * c + 2] + r.z), 0.f);
    float h3 = fmaxf(fmaf(acc.w, inv, sbc[4 * c + 3] + r.w), 0.f);
    // broadcast the 4 h-chunks so every lane holds full h[0:16]
    float hv[16];
    int basel = lane & ~3;
#pragma unroll
    for (int q = 0; q < 4; q++) {
        hv[4 * q + 0] = __shfl_sync(~0u, h0, basel | q);
        hv[4 * q + 1] = __shfl_sync(~0u, h1, basel | q);
        hv[4 * q + 2] = __shfl_sync(~0u, h2, basel | q);
        hv[4 * q + 3] = __shfl_sync(~0u, h3, basel | q);
    }
    // 16->32 GEMM: lane = output column
    float o = (lane < 16) ? sbo[lane] : 0.f;
#pragma unroll
    for (int k = 0; k < 16; k++)
        o = fmaf(hv[k], sw[k * 32 + lane], o);
    out[(size_t)w * 32 + lane] = o;   // coalesced 128B per warp
}

// per edge: z = relu(a[src] + b[dst]) ; o = z @ fc2 + fc2_b ; log_softmax
__global__ void k_edge(const int* __restrict__ ei,
                       const float* __restrict__ fc2w,
                       const float* __restrict__ fc2b,
                       float* __restrict__ out) {
    __shared__ float sf[34];
    if (threadIdx.x < 32) sf[threadIdx.x] = fc2w[threadIdx.x];
    if (threadIdx.x < 2)  sf[32 + threadIdx.x] = fc2b[threadIdx.x];
    __syncthreads();
    int e = blockIdx.x * blockDim.x + threadIdx.x;
    if (e >= N_EDGES) return;
    int s = __ldg(ei + e);
    int d = __ldg(ei + N_EDGES + e);
    const float4* ap = (const float4*)(g_bufA + (size_t)s * 32);       // a = h_s@fc1_top + fc1_b
    const float4* bp = (const float4*)(g_bufA + (size_t)d * 32 + 16);  // b = h_d@fc1_bot
    float o0 = sf[32], o1 = sf[33];
#pragma unroll
    for (int q = 0; q < 4; q++) {
        float4 a = ap[q];
        float4 b = bp[q];
        float z0 = fmaxf(a.x + b.x, 0.f);
        float z1 = fmaxf(a.y + b.y, 0.f);
        float z2 = fmaxf(a.z + b.z, 0.f);
        float z3 = fmaxf(a.w + b.w, 0.f);
        int j = q * 4;
        o0 = fmaf(z0, sf[(j + 0) * 2 + 0], o0);  o1 = fmaf(z0, sf[(j + 0) * 2 + 1], o1);
        o0 = fmaf(z1, sf[(j + 1) * 2 + 0], o0);  o1 = fmaf(z1, sf[(j + 1) * 2 + 1], o1);
        o0 = fmaf(z2, sf[(j + 2) * 2 + 0], o0);  o1 = fmaf(z2, sf[(j + 2) * 2 + 1], o1);
        o0 = fmaf(z3, sf[(j + 3) * 2 + 0], o0);  o1 = fmaf(z3, sf[(j + 3) * 2 + 1], o1);
    }
    float m = fmaxf(o0, o1);
    float l = m + __logf(__expf(o0 - m) + __expf(o1 - m));
    ((float2*)out)[e] = make_float2(o0 - l, o1 - l);
}

// ---------------- launch ----------------

extern "C" void kernel_launch(void* const* d_in, const int* in_sizes, int n_in,
                              void* d_out, int out_size) {
    const float* x    = (const float*)d_in[0];
    const int*   ei   = (const int*)  d_in[1];
    const float* w1l  = (const float*)d_in[2];
    const float* b1l  = (const float*)d_in[3];
    const float* w1r  = (const float*)d_in[4];
    const float* w2l  = (const float*)d_in[5];
    const float* b2l  = (const float*)d_in[6];
    const float* w2r  = (const float*)d_in[7];
    const float* fc1w = (const float*)d_in[8];
    const float* fc1b = (const float*)d_in[9];
    const float* fc2w = (const float*)d_in[10];
    const float* fc2b = (const float*)d_in[11];
    float* out = (float*)d_out;

    const int TB = 256;
    int gN  = (N_NODES + TB - 1) / TB;        // 391
    int gE  = (N_EDGES + TB - 1) / TB;        // 12500
    int gW  = (N_NODES * 32 + TB - 1) / TB;   // warp-per-node grid: 12500
    int gG  = (N_NODES + 127) / 128;

    // CSR build (per call; deterministic work)
    k_zero_deg<<<gN, TB>>>();
    k_count<<<gE, TB>>>(ei);
    k_scan1<<<NB1, 256>>>();
    k_scan2<<<1, 512>>>();
    k_scan3<<<gN, TB>>>();
    k_fill<<<gE, TB>>>(ei);

    // dense input transform: A = x @ [w1_l|w1_r]
    k_gemm_in<<<gG, 128>>>(x, w1l, w1r);

    // layer 1: gather-mean(A.y) + b1l + A.r, relu, @[w2_l|w2_r] -> B
    k_agg<<<gW, TB>>>(0, w2l, w2r, b1l, nullptr, 0);
    // layer 2: gather-mean(B.y) + b2l + B.r, relu, @[fc1_top|fc1_bot] (+fc1_b on a) -> A
    k_agg<<<gW, TB>>>(1, fc1w, fc1w, b2l, fc1b, 16);

    // per-edge head + log_softmax
    k_edge<<<gE, TB>>>(ei, fc2w, fc2b, out);
}